// round 16
// baseline (speedup 1.0000x reference)
#include <cuda_runtime.h>
#include <float.h>
#include <math.h>

#define BB 32
#define NN 24564
#define NC 21
#define TOPKK 200
#define NMSOUT 50
#define CONF_T 0.5f
#define IOU_T 0.45f
#define CAP 512
#define FAST_FLOOR 0.98f
#define CAPF 256
#define ROWS_PER_B (NC * NMSOUT) /* 1050 */

// Scratch (static device globals; no runtime allocation)
__device__ float  g_scores[(size_t)BB * NC * NN];   // transposed conf (B, C, N)
__device__ float4 g_boxes[(size_t)BB * NN];          // decoded boxes
__device__ float  g_rows[(size_t)BB * ROWS_PER_B * 6];
__device__ float  g_sc[(size_t)BB * ROWS_PER_B];

// ---------------------------------------------------------------------------
// Kernel 1: decode boxes + transpose conf to (B, C, N)
//           staging now uses float4 (4x fewer LDG/STS); rest proven verbatim
// ---------------------------------------------------------------------------
__global__ __launch_bounds__(256) void k_decode(const float* __restrict__ pred) {
    __shared__ float stage[8][33 * 32];
    const int b = blockIdx.y;
    const int w = threadIdx.x >> 5, lane = threadIdx.x & 31;
    const int a0 = blockIdx.x * 256 + w * 32;

    const float* P = pred + (size_t)b * NN * 33;
    const long base = (long)a0 * 33;          // multiple of 32*33 -> 16B aligned
    {
        const float4* __restrict__ P4 = (const float4*)(P + base);
        float4* st4 = (float4*)&stage[w][0];
        const long lim4 = ((long)NN * 33 - base) / 4;   // NN*33 % 4 == 0
#pragma unroll
        for (int k = lane; k < 264; k += 32) {
            st4[k] = (k < lim4) ? P4[k] : make_float4(0.f, 0.f, 0.f, 0.f);
        }
    }
    __syncwarp();

    const int a = a0 + lane;
    if (a < NN) {
        const float* r = &stage[w][lane * 33];
        float l0 = r[21], l1 = r[22], l2 = r[23], l3 = r[24];
        float ax = r[25], ay = r[26], aw = r[27], ah = r[28];
        float v0 = r[29], v1 = r[30], v2 = r[31], v3 = r[32];
        float cx = l0 * aw * v0 + ax;
        float cy = l1 * ah * v1 + ay;
        float wb = expf(l2 * v2) * aw;
        float hb = expf(l3 * v3) * ah;
        float xmin = (cx - 0.5f * wb) * 512.0f;
        float xmax = (cx + 0.5f * wb) * 512.0f;
        float ymin = (cy - 0.5f * hb) * 512.0f;
        float ymax = (cy + 0.5f * hb) * 512.0f;
        g_boxes[(size_t)b * NN + a] = make_float4(xmin, ymin, xmax, ymax);
#pragma unroll
        for (int c = 0; c < NC; c++)
            g_scores[((size_t)b * NC + c) * NN + a] = r[c];
    }
}

// ---------------------------------------------------------------------------
// Kernel 2: per (b,c): fast fixed-floor compact (fallback: histogram),
//           dynamic-width bitonic sort, block NMS (R8-proven, 2 barriers/step)
// ---------------------------------------------------------------------------
__global__ __launch_bounds__(256) void k_nms() {
    const int bc = blockIdx.x;
    const int b = bc / NC, c = bc % NC;
    const float* __restrict__ S = g_scores + ((size_t)b * NC + c) * NN;
    const int tid = threadIdx.x;

    __shared__ unsigned hist[256];
    __shared__ unsigned suf[257];
    __shared__ int s_bin, s_K, s_under, s_exit;
    __shared__ unsigned s_cnt;
    __shared__ float cs[CAP];
    __shared__ int   ci[CAP];
    __shared__ float4 bx[TOPKK];
    __shared__ unsigned alive[7];
    __shared__ int s_piv;
    __shared__ int sel[NMSOUT];
    __shared__ unsigned char valf[NMSOUT];

    // ---- FAST PATH: single compact pass with fixed floor ----
    if (tid == 0) s_cnt = 0u;
    __syncthreads();
    for (int n = tid; n < NN; n += 256) {
        float s = S[n];
        if (s > FAST_FLOOR) {
            unsigned p = atomicAdd(&s_cnt, 1u);
            if (p < CAP) { cs[p] = s; ci[p] = n; }
        }
    }
    __syncthreads();
    const unsigned fastcnt = s_cnt;
    const bool fast_ok = (fastcnt >= (unsigned)TOPKK) && (fastcnt <= (unsigned)CAP);

    if (!fast_ok) {
        // ---- FALLBACK Phase A: proven histogram refinement w/ early exit ----
        int K = TOPKK;
        unsigned prefix = 0;
        bool under = false;
        unsigned offstar = 1u;

        for (int pass = 0; pass < 3; pass++) {
            const int nb = (pass == 2) ? 128 : 256;
            for (int i = tid; i < 256; i += 256) hist[i] = 0u;
            if (tid == 0) s_exit = 0;
            __syncthreads();
            for (int n = tid; n < NN; n += 256) {
                float s = S[n];
                if (s > CONF_T) {
                    unsigned off = __float_as_uint(s) - 0x3F000000u;
                    if (off > 0x7FFFFFu) off = 0x7FFFFFu;
                    if (pass == 0) {
                        atomicAdd(&hist[off >> 15], 1u);
                    } else if (pass == 1) {
                        if ((off >> 15) == prefix) atomicAdd(&hist[(off >> 7) & 0xFFu], 1u);
                    } else {
                        if ((off >> 7) == prefix) atomicAdd(&hist[off & 0x7Fu], 1u);
                    }
                }
            }
            __syncthreads();
            if (tid <= nb) {
                unsigned sum = 0;
                for (int j = tid; j < nb; j++) sum += hist[j];
                suf[tid] = sum;
            }
            if (tid == 0) suf[nb] = 0u;
            __syncthreads();
            if (pass == 0) {
                if (tid == 0) s_under = (suf[0] < (unsigned)K) ? 1 : 0;
                __syncthreads();
                if (s_under) { under = true; break; }
            }
            if (tid < nb) {
                if (suf[tid] >= (unsigned)K && suf[tid + 1] < (unsigned)K) {
                    s_bin = tid;
                    s_K = K - (int)suf[tid + 1];
                    if ((unsigned)(TOPKK - K) + suf[tid] <= (unsigned)CAP) s_exit = 1;
                }
            }
            __syncthreads();
            if (s_exit) {
                if (pass == 0)      offstar = ((unsigned)s_bin) << 15;
                else if (pass == 1) offstar = ((prefix << 8) | (unsigned)s_bin) << 7;
                else                offstar = (prefix << 7) | (unsigned)s_bin;
                break;
            }
            if (pass == 0)      prefix = (unsigned)s_bin;
            else if (pass == 1) prefix = (prefix << 8) | (unsigned)s_bin;
            else                offstar = (prefix << 7) | (unsigned)s_bin;
            K = s_K;
            __syncthreads();
        }
        if (under) offstar = 1u;

        // ---- FALLBACK Phase B: compact with offstar floor ----
        __syncthreads();
        if (tid == 0) s_cnt = 0u;
        __syncthreads();
        for (int n = tid; n < NN; n += 256) {
            float s = S[n];
            if (s > CONF_T) {
                unsigned off = __float_as_uint(s) - 0x3F000000u;
                if (off > 0x7FFFFFu) off = 0x7FFFFFu;
                if (off >= offstar) {
                    unsigned p = atomicAdd(&s_cnt, 1u);
                    if (p < CAP) { cs[p] = s; ci[p] = n; }
                }
            }
        }
        __syncthreads();
    }

    const unsigned cnt = (s_cnt < CAP) ? s_cnt : CAP;
    for (int i = tid; i < CAP; i += 256) {
        if ((unsigned)i >= cnt) { cs[i] = -FLT_MAX; ci[i] = 0x7FFFFFFF; }
    }
    __syncthreads();

    // ---- Phase C: bitonic sort over SN = next_pow2(max(cnt,256)) ----
    int SN = 256;
    while (SN < (int)cnt) SN <<= 1;
    for (int k = 2; k <= SN; k <<= 1) {
        for (int j = k >> 1; j > 0; j >>= 1) {
            for (int i = tid; i < SN; i += 256) {
                int x = i ^ j;
                if (x > i) {
                    float a = cs[i], d = cs[x];
                    int ia = ci[i], ib = ci[x];
                    bool a_first = (a > d) || (a == d && ia < ib);
                    bool up = ((i & k) == 0);
                    if (up != a_first) {
                        cs[i] = d; ci[i] = ib;
                        cs[x] = a; ci[x] = ia;
                    }
                }
            }
            __syncthreads();
        }
    }

    // ---- Phase D: gather top-200 boxes + init alive mask ----
    if (tid < TOPKK) {
        int id = ci[tid];
        bx[tid] = (id >= 0 && id < NN) ? g_boxes[(size_t)b * NN + id]
                                       : make_float4(0.f, 0.f, 0.f, 0.f);
    }
    const int A = ((int)cnt < TOPKK) ? (int)cnt : TOPKK;
    if (tid < 7) {
        int lo = tid * 32;
        unsigned m = 0u;
        if (A >= lo + 32) m = 0xFFFFFFFFu;
        else if (A > lo)  m = (1u << (A - lo)) - 1u;
        alive[tid] = m;
    }
    __syncthreads();

    // ---- Phase E: block NMS (R8-proven: thread-0 pivot, 2 barriers/step) ----
    for (int k = 0; k < NMSOUT; k++) {
        if (tid == 0) {
            int p = -1;
#pragma unroll
            for (int w2 = 0; w2 < 7; w2++)
                if (p < 0 && alive[w2]) p = w2 * 32 + __ffs(alive[w2]) - 1;
            s_piv = p;
            if (p >= 0) {
                sel[k] = p; valf[k] = 1;
                alive[p >> 5] &= ~(1u << (p & 31));
            } else {
                sel[k] = 0; valf[k] = 0;
            }
        }
        __syncthreads();
        const int p = s_piv;
        if (p >= 0) {
            bool supr = false;
            if (tid < A) {
                float4 pb = bx[p];
                float4 q = bx[tid];
                float x1 = fmaxf(pb.x, q.x), y1 = fmaxf(pb.y, q.y);
                float x2 = fminf(pb.z, q.z), y2 = fminf(pb.w, q.w);
                float inter = fmaxf(x2 - x1, 0.0f) * fmaxf(y2 - y1, 0.0f);
                float ap = (pb.z - pb.x) * (pb.w - pb.y);
                float aq = (q.z - q.x) * (q.w - q.y);
                float iou = inter / (ap + aq - inter + 1e-8f);
                supr = (iou > IOU_T);
            }
            unsigned m = __ballot_sync(0xFFFFFFFFu, supr);
            if ((tid & 31) == 0 && (tid >> 5) < 7 && m)
                alive[tid >> 5] &= ~m;
        }
        __syncthreads();
    }

    // ---- Phase F: write rows + compact score column  [proven verbatim] ----
    for (int e = tid; e < NMSOUT * 6; e += 256) {
        int r = e / 6, col = e % 6;
        float v = 0.0f;
        if (valf[r]) {
            int i = sel[r];
            if (col == 0)      v = (float)c;
            else if (col == 1) v = cs[i];
            else {
                float4 B2 = bx[i];
                v = (col == 2) ? B2.x : (col == 3) ? B2.y : (col == 4) ? B2.z : B2.w;
            }
        }
        g_rows[((size_t)bc * NMSOUT + r) * 6 + col] = v;
    }
    for (int r = tid; r < NMSOUT; r += 256)
        g_sc[(size_t)bc * NMSOUT + r] = valf[r] ? cs[sel[r]] : 0.0f;
}

// ---------------------------------------------------------------------------
// Kernel 3: per-batch top-200 of 1050 rows  [R8 proven verbatim]
// ---------------------------------------------------------------------------
__global__ __launch_bounds__(256) void k_final(float* __restrict__ out) {
    const int b = blockIdx.x;
    const int tid = threadIdx.x;

    __shared__ float sc[ROWS_PER_B];
    __shared__ unsigned hist[256];
    __shared__ unsigned suf[257];
    __shared__ int s_bin, s_K, s_under, s_exit;
    __shared__ unsigned s_cnt;
    __shared__ float cs2[CAPF];
    __shared__ int   ci2[CAPF];

    for (int i = tid; i < ROWS_PER_B; i += 256)
        sc[i] = g_sc[(size_t)b * ROWS_PER_B + i];
    __syncthreads();

    int K = TOPKK;
    unsigned prefix = 0;
    bool under = false;
    unsigned offstar = 1u;

    for (int pass = 0; pass < 3; pass++) {
        const int nb = (pass == 2) ? 128 : 256;
        for (int i = tid; i < 256; i += 256) hist[i] = 0u;
        if (tid == 0) s_exit = 0;
        __syncthreads();
        for (int n = tid; n < ROWS_PER_B; n += 256) {
            float s = sc[n];
            if (s > CONF_T) {
                unsigned off = __float_as_uint(s) - 0x3F000000u;
                if (off > 0x7FFFFFu) off = 0x7FFFFFu;
                if (pass == 0) {
                    atomicAdd(&hist[off >> 15], 1u);
                } else if (pass == 1) {
                    if ((off >> 15) == prefix) atomicAdd(&hist[(off >> 7) & 0xFFu], 1u);
                } else {
                    if ((off >> 7) == prefix) atomicAdd(&hist[off & 0x7Fu], 1u);
                }
            }
        }
        __syncthreads();
        if (tid <= nb) {
            unsigned sum = 0;
            for (int j = tid; j < nb; j++) sum += hist[j];
            suf[tid] = sum;
        }
        if (tid == 0) suf[nb] = 0u;
        __syncthreads();
        if (pass == 0) {
            if (tid == 0) s_under = (suf[0] < (unsigned)K) ? 1 : 0;
            __syncthreads();
            if (s_under) { under = true; break; }
        }
        if (tid < nb) {
            if (suf[tid] >= (unsigned)K && suf[tid + 1] < (unsigned)K) {
                s_bin = tid;
                s_K = K - (int)suf[tid + 1];
                if ((unsigned)(TOPKK - K) + suf[tid] <= (unsigned)CAPF) s_exit = 1;
            }
        }
        __syncthreads();
        if (s_exit) {
            if (pass == 0)      offstar = ((unsigned)s_bin) << 15;
            else if (pass == 1) offstar = ((prefix << 8) | (unsigned)s_bin) << 7;
            else                offstar = (prefix << 7) | (unsigned)s_bin;
            break;
        }
        if (pass == 0)      prefix = (unsigned)s_bin;
        else if (pass == 1) prefix = (prefix << 8) | (unsigned)s_bin;
        else                offstar = (prefix << 7) | (unsigned)s_bin;
        K = s_K;
        __syncthreads();
    }
    if (under) offstar = 1u;

    if (tid == 0) s_cnt = 0u;
    __syncthreads();
    for (int n = tid; n < ROWS_PER_B; n += 256) {
        float s = sc[n];
        if (s > CONF_T) {
            unsigned off = __float_as_uint(s) - 0x3F000000u;
            if (off > 0x7FFFFFu) off = 0x7FFFFFu;
            if (off >= offstar) {
                unsigned p = atomicAdd(&s_cnt, 1u);
                if (p < (unsigned)CAPF) { cs2[p] = s; ci2[p] = n; }
            }
        }
    }
    __syncthreads();
    if (tid == 0 && s_cnt < (unsigned)TOPKK) {
        unsigned k2 = s_cnt;
        for (int n = 0; n < ROWS_PER_B && k2 < (unsigned)TOPKK; n++) {
            if (!(sc[n] > CONF_T)) { cs2[k2] = sc[n]; ci2[k2] = n; k2++; }
        }
        s_cnt = k2;
    }
    __syncthreads();
    const unsigned cnt = (s_cnt < (unsigned)CAPF) ? s_cnt : (unsigned)CAPF;
    for (int i = tid; i < CAPF; i += 256)
        if ((unsigned)i >= cnt) { cs2[i] = -FLT_MAX; ci2[i] = 0x7FFFFFFF; }
    __syncthreads();

    for (int k = 2; k <= CAPF; k <<= 1) {
        for (int j = k >> 1; j > 0; j >>= 1) {
            for (int i = tid; i < CAPF; i += 256) {
                int x = i ^ j;
                if (x > i) {
                    float a = cs2[i], d = cs2[x];
                    int ia = ci2[i], ib = ci2[x];
                    bool a_first = (a > d) || (a == d && ia < ib);
                    bool up = ((i & k) == 0);
                    if (up != a_first) {
                        cs2[i] = d; ci2[i] = ib;
                        cs2[x] = a; ci2[x] = ia;
                    }
                }
            }
            __syncthreads();
        }
    }

    for (int e = tid; e < TOPKK * 6; e += 256) {
        int r = e / 6, col = e % 6;
        int src = ci2[r];
        if (src < 0 || src >= ROWS_PER_B) src = 0;
        out[(size_t)b * TOPKK * 6 + e] =
            g_rows[((size_t)b * ROWS_PER_B + src) * 6 + col];
    }
}

extern "C" void kernel_launch(void* const* d_in, const int* in_sizes, int n_in,
                              void* d_out, int out_size) {
    const float* pred = (const float*)d_in[0];
    float* out = (float*)d_out;
    dim3 g1((NN + 255) / 256, BB);
    k_decode<<<g1, 256>>>(pred);
    k_nms<<<BB * NC, 256>>>();
    k_final<<<BB, 256>>>(out);
}

// round 17
// speedup vs baseline: 1.0933x; 1.0933x over previous
#include <cuda_runtime.h>
#include <float.h>
#include <math.h>

#define BB 32
#define NN 24564
#define NC 21
#define TOPKK 200
#define NMSOUT 50
#define CONF_T 0.5f
#define IOU_T 0.45f
#define CAP 1024
#define FAST_FLOOR 0.98f
#define CAPF 256
#define NWARP 768            /* warps per batch: 96 blocks x 8 warps */
#define ROWS_PER_B (NC * NMSOUT) /* 1050 */

// Scratch (static device globals; no runtime allocation)
__device__ unsigned g_mask[(size_t)BB * NC * NWARP]; // candidate ballot bits
__device__ float4   g_boxes[(size_t)BB * NN];         // decoded boxes
__device__ float    g_rows[(size_t)BB * ROWS_PER_B * 6];
__device__ float    g_sc[(size_t)BB * ROWS_PER_B];

// ---------------------------------------------------------------------------
// Kernel 1: decode boxes + per-class candidate ballot masks (s > FAST_FLOOR)
//           (R1-proven scalar staging; score transpose write REMOVED)
// ---------------------------------------------------------------------------
__global__ __launch_bounds__(256) void k_decode(const float* __restrict__ pred) {
    __shared__ float stage[8][33 * 32];
    const int b = blockIdx.y;
    const int w = threadIdx.x >> 5, lane = threadIdx.x & 31;
    const int a0 = blockIdx.x * 256 + w * 32;

    const float* P = pred + (size_t)b * NN * 33;
    const long base = (long)a0 * 33;
#pragma unroll
    for (int k = 0; k < 33; k++) {
        long e = base + k * 32 + lane;
        stage[w][k * 32 + lane] = (e < (long)NN * 33) ? P[e] : 0.0f;
    }
    __syncwarp();

    const int a = a0 + lane;
    const bool act = (a < NN);
    const float* r = &stage[w][lane * 33];

    if (act) {
        float l0 = r[21], l1 = r[22], l2 = r[23], l3 = r[24];
        float ax = r[25], ay = r[26], aw = r[27], ah = r[28];
        float v0 = r[29], v1 = r[30], v2 = r[31], v3 = r[32];
        float cx = l0 * aw * v0 + ax;
        float cy = l1 * ah * v1 + ay;
        float wb = expf(l2 * v2) * aw;
        float hb = expf(l3 * v3) * ah;
        float xmin = (cx - 0.5f * wb) * 512.0f;
        float xmax = (cx + 0.5f * wb) * 512.0f;
        float ymin = (cy - 0.5f * hb) * 512.0f;
        float ymax = (cy + 0.5f * hb) * 512.0f;
        g_boxes[(size_t)b * NN + a] = make_float4(xmin, ymin, xmax, ymax);
    }

    // Candidate ballot per class; lane c keeps ballot c; one STG per class.
    const int wid = blockIdx.x * 8 + w;   // [0, NWARP)
    unsigned myball = 0u;
#pragma unroll
    for (int c = 0; c < NC; c++) {
        bool pass = act && (r[c] > FAST_FLOOR);
        unsigned m = __ballot_sync(0xFFFFFFFFu, pass);
        if (lane == c) myball = m;
    }
    if (lane < NC)
        g_mask[((size_t)b * NC + lane) * NWARP + wid] = myball;
}

// ---------------------------------------------------------------------------
// Kernel 2: per (b,c): mask-driven candidate gather (fallback: histogram over
//           strided pred), bitonic sort, block NMS (R8-proven).
// ---------------------------------------------------------------------------
__global__ __launch_bounds__(256) void k_nms(const float* __restrict__ pred) {
    const int bc = blockIdx.x;
    const int b = bc / NC, c = bc % NC;
    const int tid = threadIdx.x;

    __shared__ unsigned hist[256];
    __shared__ unsigned suf[257];
    __shared__ int s_bin, s_K, s_under, s_exit;
    __shared__ unsigned s_cnt;
    __shared__ float cs[CAP];
    __shared__ int   ci[CAP];
    __shared__ float4 bx[TOPKK];
    __shared__ unsigned alive[7];
    __shared__ int s_piv;
    __shared__ int sel[NMSOUT];
    __shared__ unsigned char valf[NMSOUT];

    // ---- FAST PATH: expand candidate bitmask, gather scores from pred ----
    if (tid == 0) s_cnt = 0u;
    __syncthreads();
    {
        const unsigned* __restrict__ M = g_mask + (size_t)bc * NWARP;
        for (int widx = tid; widx < NWARP; widx += 256) {
            unsigned m = M[widx];
            while (m) {
                int bit = __ffs(m) - 1;
                m &= m - 1;
                int a = widx * 32 + bit;
                unsigned p = atomicAdd(&s_cnt, 1u);
                if (p < CAP) {
                    ci[p] = a;
                    cs[p] = pred[((size_t)b * NN + a) * 33 + c];
                }
            }
        }
    }
    __syncthreads();
    const unsigned fastcnt = s_cnt;
    const bool fast_ok = (fastcnt >= (unsigned)TOPKK) && (fastcnt <= (unsigned)CAP);

    if (!fast_ok) {
        // ---- FALLBACK: histogram refinement over strided pred scores ----
        const float* __restrict__ SP = pred + (size_t)b * NN * 33 + c;
        int K = TOPKK;
        unsigned prefix = 0;
        bool under = false;
        unsigned offstar = 1u;

        for (int pass = 0; pass < 3; pass++) {
            const int nb = (pass == 2) ? 128 : 256;
            for (int i = tid; i < 256; i += 256) hist[i] = 0u;
            if (tid == 0) s_exit = 0;
            __syncthreads();
            for (int n = tid; n < NN; n += 256) {
                float s = SP[(size_t)n * 33];
                if (s > CONF_T) {
                    unsigned off = __float_as_uint(s) - 0x3F000000u;
                    if (off > 0x7FFFFFu) off = 0x7FFFFFu;
                    if (pass == 0) {
                        atomicAdd(&hist[off >> 15], 1u);
                    } else if (pass == 1) {
                        if ((off >> 15) == prefix) atomicAdd(&hist[(off >> 7) & 0xFFu], 1u);
                    } else {
                        if ((off >> 7) == prefix) atomicAdd(&hist[off & 0x7Fu], 1u);
                    }
                }
            }
            __syncthreads();
            if (tid <= nb) {
                unsigned sum = 0;
                for (int j = tid; j < nb; j++) sum += hist[j];
                suf[tid] = sum;
            }
            if (tid == 0) suf[nb] = 0u;
            __syncthreads();
            if (pass == 0) {
                if (tid == 0) s_under = (suf[0] < (unsigned)K) ? 1 : 0;
                __syncthreads();
                if (s_under) { under = true; break; }
            }
            if (tid < nb) {
                if (suf[tid] >= (unsigned)K && suf[tid + 1] < (unsigned)K) {
                    s_bin = tid;
                    s_K = K - (int)suf[tid + 1];
                    if ((unsigned)(TOPKK - K) + suf[tid] <= (unsigned)CAP) s_exit = 1;
                }
            }
            __syncthreads();
            if (s_exit) {
                if (pass == 0)      offstar = ((unsigned)s_bin) << 15;
                else if (pass == 1) offstar = ((prefix << 8) | (unsigned)s_bin) << 7;
                else                offstar = (prefix << 7) | (unsigned)s_bin;
                break;
            }
            if (pass == 0)      prefix = (unsigned)s_bin;
            else if (pass == 1) prefix = (prefix << 8) | (unsigned)s_bin;
            else                offstar = (prefix << 7) | (unsigned)s_bin;
            K = s_K;
            __syncthreads();
        }
        if (under) offstar = 1u;

        __syncthreads();
        if (tid == 0) s_cnt = 0u;
        __syncthreads();
        for (int n = tid; n < NN; n += 256) {
            float s = SP[(size_t)n * 33];
            if (s > CONF_T) {
                unsigned off = __float_as_uint(s) - 0x3F000000u;
                if (off > 0x7FFFFFu) off = 0x7FFFFFu;
                if (off >= offstar) {
                    unsigned p = atomicAdd(&s_cnt, 1u);
                    if (p < CAP) { cs[p] = s; ci[p] = n; }
                }
            }
        }
        __syncthreads();
    }

    const unsigned cnt = (s_cnt < CAP) ? s_cnt : CAP;
    for (int i = tid; i < CAP; i += 256) {
        if ((unsigned)i >= cnt) { cs[i] = -FLT_MAX; ci[i] = 0x7FFFFFFF; }
    }
    __syncthreads();

    // ---- Phase C: bitonic sort over SN = next_pow2(max(cnt,256)) ----
    int SN = 256;
    while (SN < (int)cnt) SN <<= 1;
    for (int k = 2; k <= SN; k <<= 1) {
        for (int j = k >> 1; j > 0; j >>= 1) {
            for (int i = tid; i < SN; i += 256) {
                int x = i ^ j;
                if (x > i) {
                    float a = cs[i], d = cs[x];
                    int ia = ci[i], ib = ci[x];
                    bool a_first = (a > d) || (a == d && ia < ib);
                    bool up = ((i & k) == 0);
                    if (up != a_first) {
                        cs[i] = d; ci[i] = ib;
                        cs[x] = a; ci[x] = ia;
                    }
                }
            }
            __syncthreads();
        }
    }

    // ---- Phase D: gather top-200 boxes + init alive mask ----
    if (tid < TOPKK) {
        int id = ci[tid];
        bx[tid] = (id >= 0 && id < NN) ? g_boxes[(size_t)b * NN + id]
                                       : make_float4(0.f, 0.f, 0.f, 0.f);
    }
    const int A = ((int)cnt < TOPKK) ? (int)cnt : TOPKK;
    if (tid < 7) {
        int lo = tid * 32;
        unsigned m = 0u;
        if (A >= lo + 32) m = 0xFFFFFFFFu;
        else if (A > lo)  m = (1u << (A - lo)) - 1u;
        alive[tid] = m;
    }
    __syncthreads();

    // ---- Phase E: block NMS (R8-proven: thread-0 pivot, 2 barriers/step) ----
    for (int k = 0; k < NMSOUT; k++) {
        if (tid == 0) {
            int p = -1;
#pragma unroll
            for (int w2 = 0; w2 < 7; w2++)
                if (p < 0 && alive[w2]) p = w2 * 32 + __ffs(alive[w2]) - 1;
            s_piv = p;
            if (p >= 0) {
                sel[k] = p; valf[k] = 1;
                alive[p >> 5] &= ~(1u << (p & 31));
            } else {
                sel[k] = 0; valf[k] = 0;
            }
        }
        __syncthreads();
        const int p = s_piv;
        if (p >= 0) {
            bool supr = false;
            if (tid < A) {
                float4 pb = bx[p];
                float4 q = bx[tid];
                float x1 = fmaxf(pb.x, q.x), y1 = fmaxf(pb.y, q.y);
                float x2 = fminf(pb.z, q.z), y2 = fminf(pb.w, q.w);
                float inter = fmaxf(x2 - x1, 0.0f) * fmaxf(y2 - y1, 0.0f);
                float ap = (pb.z - pb.x) * (pb.w - pb.y);
                float aq = (q.z - q.x) * (q.w - q.y);
                float iou = inter / (ap + aq - inter + 1e-8f);
                supr = (iou > IOU_T);
            }
            unsigned m = __ballot_sync(0xFFFFFFFFu, supr);
            if ((tid & 31) == 0 && (tid >> 5) < 7 && m)
                alive[tid >> 5] &= ~m;
        }
        __syncthreads();
    }

    // ---- Phase F: write rows + compact score column  [proven verbatim] ----
    for (int e = tid; e < NMSOUT * 6; e += 256) {
        int r = e / 6, col = e % 6;
        float v = 0.0f;
        if (valf[r]) {
            int i = sel[r];
            if (col == 0)      v = (float)c;
            else if (col == 1) v = cs[i];
            else {
                float4 B2 = bx[i];
                v = (col == 2) ? B2.x : (col == 3) ? B2.y : (col == 4) ? B2.z : B2.w;
            }
        }
        g_rows[((size_t)bc * NMSOUT + r) * 6 + col] = v;
    }
    for (int r = tid; r < NMSOUT; r += 256)
        g_sc[(size_t)bc * NMSOUT + r] = valf[r] ? cs[sel[r]] : 0.0f;
}

// ---------------------------------------------------------------------------
// Kernel 3: per-batch top-200 of 1050 rows  [R8 proven verbatim]
// ---------------------------------------------------------------------------
__global__ __launch_bounds__(256) void k_final(float* __restrict__ out) {
    const int b = blockIdx.x;
    const int tid = threadIdx.x;

    __shared__ float sc[ROWS_PER_B];
    __shared__ unsigned hist[256];
    __shared__ unsigned suf[257];
    __shared__ int s_bin, s_K, s_under, s_exit;
    __shared__ unsigned s_cnt;
    __shared__ float cs2[CAPF];
    __shared__ int   ci2[CAPF];

    for (int i = tid; i < ROWS_PER_B; i += 256)
        sc[i] = g_sc[(size_t)b * ROWS_PER_B + i];
    __syncthreads();

    int K = TOPKK;
    unsigned prefix = 0;
    bool under = false;
    unsigned offstar = 1u;

    for (int pass = 0; pass < 3; pass++) {
        const int nb = (pass == 2) ? 128 : 256;
        for (int i = tid; i < 256; i += 256) hist[i] = 0u;
        if (tid == 0) s_exit = 0;
        __syncthreads();
        for (int n = tid; n < ROWS_PER_B; n += 256) {
            float s = sc[n];
            if (s > CONF_T) {
                unsigned off = __float_as_uint(s) - 0x3F000000u;
                if (off > 0x7FFFFFu) off = 0x7FFFFFu;
                if (pass == 0) {
                    atomicAdd(&hist[off >> 15], 1u);
                } else if (pass == 1) {
                    if ((off >> 15) == prefix) atomicAdd(&hist[(off >> 7) & 0xFFu], 1u);
                } else {
                    if ((off >> 7) == prefix) atomicAdd(&hist[off & 0x7Fu], 1u);
                }
            }
        }
        __syncthreads();
        if (tid <= nb) {
            unsigned sum = 0;
            for (int j = tid; j < nb; j++) sum += hist[j];
            suf[tid] = sum;
        }
        if (tid == 0) suf[nb] = 0u;
        __syncthreads();
        if (pass == 0) {
            if (tid == 0) s_under = (suf[0] < (unsigned)K) ? 1 : 0;
            __syncthreads();
            if (s_under) { under = true; break; }
        }
        if (tid < nb) {
            if (suf[tid] >= (unsigned)K && suf[tid + 1] < (unsigned)K) {
                s_bin = tid;
                s_K = K - (int)suf[tid + 1];
                if ((unsigned)(TOPKK - K) + suf[tid] <= (unsigned)CAPF) s_exit = 1;
            }
        }
        __syncthreads();
        if (s_exit) {
            if (pass == 0)      offstar = ((unsigned)s_bin) << 15;
            else if (pass == 1) offstar = ((prefix << 8) | (unsigned)s_bin) << 7;
            else                offstar = (prefix << 7) | (unsigned)s_bin;
            break;
        }
        if (pass == 0)      prefix = (unsigned)s_bin;
        else if (pass == 1) prefix = (prefix << 8) | (unsigned)s_bin;
        else                offstar = (prefix << 7) | (unsigned)s_bin;
        K = s_K;
        __syncthreads();
    }
    if (under) offstar = 1u;

    if (tid == 0) s_cnt = 0u;
    __syncthreads();
    for (int n = tid; n < ROWS_PER_B; n += 256) {
        float s = sc[n];
        if (s > CONF_T) {
            unsigned off = __float_as_uint(s) - 0x3F000000u;
            if (off > 0x7FFFFFu) off = 0x7FFFFFu;
            if (off >= offstar) {
                unsigned p = atomicAdd(&s_cnt, 1u);
                if (p < (unsigned)CAPF) { cs2[p] = s; ci2[p] = n; }
            }
        }
    }
    __syncthreads();
    if (tid == 0 && s_cnt < (unsigned)TOPKK) {
        unsigned k2 = s_cnt;
        for (int n = 0; n < ROWS_PER_B && k2 < (unsigned)TOPKK; n++) {
            if (!(sc[n] > CONF_T)) { cs2[k2] = sc[n]; ci2[k2] = n; k2++; }
        }
        s_cnt = k2;
    }
    __syncthreads();
    const unsigned cnt = (s_cnt < (unsigned)CAPF) ? s_cnt : (unsigned)CAPF;
    for (int i = tid; i < CAPF; i += 256)
        if ((unsigned)i >= cnt) { cs2[i] = -FLT_MAX; ci2[i] = 0x7FFFFFFF; }
    __syncthreads();

    for (int k = 2; k <= CAPF; k <<= 1) {
        for (int j = k >> 1; j > 0; j >>= 1) {
            for (int i = tid; i < CAPF; i += 256) {
                int x = i ^ j;
                if (x > i) {
                    float a = cs2[i], d = cs2[x];
                    int ia = ci2[i], ib = ci2[x];
                    bool a_first = (a > d) || (a == d && ia < ib);
                    bool up = ((i & k) == 0);
                    if (up != a_first) {
                        cs2[i] = d; ci2[i] = ib;
                        cs2[x] = a; ci2[x] = ia;
                    }
                }
            }
            __syncthreads();
        }
    }

    for (int e = tid; e < TOPKK * 6; e += 256) {
        int r = e / 6, col = e % 6;
        int src = ci2[r];
        if (src < 0 || src >= ROWS_PER_B) src = 0;
        out[(size_t)b * TOPKK * 6 + e] =
            g_rows[((size_t)b * ROWS_PER_B + src) * 6 + col];
    }
}

extern "C" void kernel_launch(void* const* d_in, const int* in_sizes, int n_in,
                              void* d_out, int out_size) {
    const float* pred = (const float*)d_in[0];
    float* out = (float*)d_out;
    dim3 g1((NN + 255) / 256, BB);
    k_decode<<<g1, 256>>>(pred);
    k_nms<<<BB * NC, 256>>>(pred);
    k_final<<<BB, 256>>>(out);
}